// round 2
// baseline (speedup 1.0000x reference)
#include <cuda_runtime.h>

// VolumeRenderer: per-ray alpha compositing.
// inputs (metadata order): density [N,128] f32, feature [N,128,3] f32, depth_values [N,128] f32
// output: concat(rgb [N,3], depth [N,3]) f32
//
// One warp per ray; lane l owns points [4l, 4l+4). All global loads are float4.
// Transmittance = exclusive multiplicative warp scan of per-lane 4-term products.

#define FULL_MASK 0xFFFFFFFFu

__global__ void __launch_bounds__(256, 8)
volume_render_kernel(const float* __restrict__ density,
                     const float* __restrict__ feature,
                     const float* __restrict__ depthv,
                     float* __restrict__ out,
                     int n_rays)
{
    const int warp_global = (int)((blockIdx.x * blockDim.x + threadIdx.x) >> 5);
    const int lane = (int)(threadIdx.x & 31u);
    if (warp_global >= n_rays) return;

    const size_t ray = (size_t)warp_global;
    constexpr int P = 128;
    constexpr float EPS = 1e-10f;
    constexpr float FAR = 1e10f;

    // ---- loads (all 16B, coalesced: warp covers 512B contiguous per vector) ----
    const float4 z  = *reinterpret_cast<const float4*>(depthv  + ray * P + lane * 4);
    const float4 dn = *reinterpret_cast<const float4*>(density + ray * P + lane * 4);
    const float4* fbase = reinterpret_cast<const float4*>(feature + ray * (size_t)(P * 3) + lane * 12);
    const float4 fA = fbase[0];   // f0.rgb, f1.r
    const float4 fB = fbase[1];   // f1.gb, f2.rg
    const float4 fC = fbase[2];   // f2.b, f3.rgb

    // ---- deltas: need next lane's first depth for this lane's last delta ----
    const float z_next = __shfl_down_sync(FULL_MASK, z.x, 1);
    const float del0 = z.y - z.x;
    const float del1 = z.z - z.y;
    const float del2 = z.w - z.z;
    const float del3 = (lane == 31) ? FAR : (z_next - z.w);

    // ---- alpha + (1 - alpha + eps) ----
    const float a0 = 1.0f - __expf(-del0 * dn.x);
    const float a1 = 1.0f - __expf(-del1 * dn.y);
    const float a2 = 1.0f - __expf(-del2 * dn.z);
    const float a3 = 1.0f - __expf(-del3 * dn.w);

    const float t0 = 1.0f - a0 + EPS;
    const float t1 = 1.0f - a1 + EPS;
    const float t2 = 1.0f - a2 + EPS;
    const float t3 = 1.0f - a3 + EPS;

    // local prefix products (exclusive within lane)
    const float p1 = t0;
    const float p2 = p1 * t1;
    const float p3 = p2 * t2;
    const float tot = p3 * t3;

    // ---- exclusive multiplicative warp scan of `tot` (shift then inclusive-scan) ----
    float s = __shfl_up_sync(FULL_MASK, tot, 1);
    if (lane == 0) s = 1.0f;
    #pragma unroll
    for (int off = 1; off < 32; off <<= 1) {
        const float v = __shfl_up_sync(FULL_MASK, s, off);
        if (lane >= off) s *= v;
    }
    // s = prod of all earlier lanes' totals = transmittance entering this lane's chunk

    // ---- weights ----
    const float w0 = s * a0;
    const float w1 = s * p1 * a1;
    const float w2 = s * p2 * a2;
    const float w3 = s * p3 * a3;

    // ---- weighted accumulation ----
    // lane's 4 features: f0=(fA.x,fA.y,fA.z) f1=(fA.w,fB.x,fB.y) f2=(fB.z,fB.w,fC.x) f3=(fC.y,fC.z,fC.w)
    float r = w0 * fA.x + w1 * fA.w + w2 * fB.z + w3 * fC.y;
    float g = w0 * fA.y + w1 * fB.x + w2 * fB.w + w3 * fC.z;
    float b = w0 * fA.z + w1 * fB.y + w2 * fC.x + w3 * fC.w;
    float d = w0 * z.x  + w1 * z.y  + w2 * z.z  + w3 * z.w;

    // ---- warp reduction ----
    #pragma unroll
    for (int off = 16; off > 0; off >>= 1) {
        r += __shfl_xor_sync(FULL_MASK, r, off);
        g += __shfl_xor_sync(FULL_MASK, g, off);
        b += __shfl_xor_sync(FULL_MASK, b, off);
        d += __shfl_xor_sync(FULL_MASK, d, off);
    }

    if (lane == 0) {
        float* rgb_out   = out;
        float* depth_out = out + (size_t)n_rays * 3;
        rgb_out[ray * 3 + 0] = r;
        rgb_out[ray * 3 + 1] = g;
        rgb_out[ray * 3 + 2] = b;
        depth_out[ray * 3 + 0] = d;
        depth_out[ray * 3 + 1] = d;
        depth_out[ray * 3 + 2] = d;
    }
}

extern "C" void kernel_launch(void* const* d_in, const int* in_sizes, int n_in,
                              void* d_out, int out_size)
{
    const float* density = (const float*)d_in[0];
    const float* feature = (const float*)d_in[1];
    const float* depthv  = (const float*)d_in[2];
    float* out = (float*)d_out;

    const int n_rays = in_sizes[0] / 128;

    const int threads = 256;                 // 8 warps = 8 rays per block
    const int rays_per_block = threads / 32;
    const int blocks = (n_rays + rays_per_block - 1) / rays_per_block;

    volume_render_kernel<<<blocks, threads>>>(density, feature, depthv, out, n_rays);
}